// round 17
// baseline (speedup 1.0000x reference)
#include <cuda_runtime.h>
#include <cuda_bf16.h>
#include <cuda_fp16.h>
#include <cstdint>
#include <math.h>

#define IN_DIM 128
#define HID    32
#define NCLS   30
#define CP     32            // logical row width (features)
#define NMAX   100000
#define EMAX   3200000
#define EPAD   4800064       // >= EMAX + 16*(NMAX+1) + 16
#define G2MAX  2048          // gather2 grid size (fixed)
#define PARTM  32768
#define REG_C  0.01

// ---------------- static scratch ----------------
__device__ float   d_g1 [NMAX * CP];          // raw gemm1 output (fp32 staging)
__device__ __half2 d_g1h[(NMAX + 1) * 16];    // g1*dinv rows, fp16 (64B) + zero row N
__device__ __half2 d_g2h[(NMAX + 1) * 16];    // g2 rows, fp16 (64B) + zero row N
__device__ __nv_bfloat162 d_fx16[NMAX * 16];
__device__ int    d_cnt [NMAX + 1];           // zeroed by ff_k tail each call
__device__ int    d_cur [NMAX + 1];
__device__ int    d_rp  [NMAX + 1];           // padded CSR row pointers (mult of 16)
__device__ int    d_src32[EMAX];
__device__ int    d_dst32[EMAX];
__device__ int    d_csr [EPAD];
__device__ float  d_dinv[NMAX];
__device__ int    d_blocksum[1024];
__device__ float  d_partialS[32 * G2MAX];
__device__ float  d_partialM[PARTM];

// ---------------- count + int32 conversion (per-block dtype detect) --------
__global__ void count_convert(const void* __restrict__ ei, int E) {
    __shared__ unsigned any_sh;
    if (threadIdx.x == 0) any_sh = 0u;
    __syncthreads();
    if (threadIdx.x < 64) {
        const unsigned int* w = (const unsigned int*)ei;
        unsigned int v = w[2 * threadIdx.x + 1];       // hi-words if int64
        unsigned int b = __ballot_sync(0xffffffffu, v != 0);
        if ((threadIdx.x & 31) == 0) atomicOr(&any_sh, b);
    }
    __syncthreads();
    bool is64 = (any_sh == 0u);

    int e = blockIdx.x * blockDim.x + threadIdx.x;
    if (e >= E) return;
    int s, d;
    if (is64) {
        const long long* p = (const long long*)ei;
        s = (int)p[e]; d = (int)p[(size_t)E + e];
    } else {
        const int* p = (const int*)ei;
        s = p[e]; d = p[(size_t)E + e];
    }
    d_src32[e] = s; d_dst32[e] = d;
    atomicAdd(&d_cnt[d], 1);
}

// ---------------- scan over 16-PADDED counts (N+1 elements) + fused dinv ---
__global__ void scan1(int N) {
    __shared__ int sh[1024];
    int gid = blockIdx.x * 1024 + threadIdx.x;
    int cnt = 0, v = 0;
    if (gid <= N) { cnt = d_cnt[gid]; v = (cnt + 15) & ~15; }
    if (gid < N) d_dinv[gid] = rsqrtf((float)(cnt + 1));    // +1 self loop
    sh[threadIdx.x] = v; __syncthreads();
    for (int off = 1; off < 1024; off <<= 1) {
        int t = (threadIdx.x >= off) ? sh[threadIdx.x - off] : 0;
        __syncthreads();
        sh[threadIdx.x] += t;
        __syncthreads();
    }
    int incl = sh[threadIdx.x];
    if (gid <= N) d_cur[gid] = incl - v;          // block-local exclusive
    if (threadIdx.x == 1023) d_blocksum[blockIdx.x] = incl;
}

// scan3: inlined block offsets + rp/cursor write + sentinel tail padding
__global__ void scan3(int N) {
    __shared__ int off_sh;
    int lane = threadIdx.x & 31;
    if (threadIdx.x < 32) {
        int s = 0;
        for (int k = lane; k < blockIdx.x; k += 32) s += d_blocksum[k];
#pragma unroll
        for (int o = 16; o; o >>= 1) s += __shfl_down_sync(0xffffffffu, s, o);
        if (lane == 0) off_sh = s;
    }
    __syncthreads();
    int gid = blockIdx.x * 1024 + threadIdx.x;
    if (gid <= N) {
        int rp = d_cur[gid] + off_sh;
        d_rp[gid] = rp;
        d_cur[gid] = rp;                           // fill cursor
        if (gid < N) {
            int c = d_cnt[gid];
            int end = rp + ((c + 15) & ~15);
            for (int p = rp + c; p < end; p++) d_csr[p] = N;   // sentinel tail
        } else {
            for (int p = rp; p < rp + 16; p++) d_csr[p] = N;   // global tail
        }
    }
}

// ---------------- CSR fill -------------------------------------------------
__global__ void fill_k(int E) {
    int e = blockIdx.x * blockDim.x + threadIdx.x;
    if (e >= E) return;
    int d = d_dst32[e];
    int pos = atomicAdd(&d_cur[d], 1);
    d_csr[pos] = d_src32[e];
}

// ---------------- GEMM1 (raw): g1 = x @ W1 (aux stream) --------------------
__global__ void gemm1_raw(const float* __restrict__ x, const float* __restrict__ W1, int N) {
    __shared__ float Ws[IN_DIM * HID];
    for (int i = threadIdx.x; i < IN_DIM * HID; i += blockDim.x) Ws[i] = W1[i];
    __syncthreads();
    int r = blockIdx.x * blockDim.x + threadIdx.x;
    if (r >= N) return;

    float acc[HID];
#pragma unroll
    for (int c = 0; c < HID; c++) acc[c] = 0.f;

    const float4* x4 = reinterpret_cast<const float4*>(x + (size_t)r * IN_DIM);
#pragma unroll 4
    for (int k4 = 0; k4 < IN_DIM / 4; k4++) {
        float4 xv = x4[k4];
        int k = k4 * 4;
#pragma unroll
        for (int c = 0; c < HID; c++) {
            acc[c] += xv.x * Ws[(k + 0) * HID + c]
                    + xv.y * Ws[(k + 1) * HID + c]
                    + xv.z * Ws[(k + 2) * HID + c]
                    + xv.w * Ws[(k + 3) * HID + c];
        }
    }
    float* out = d_g1 + (size_t)r * CP;
#pragma unroll
    for (int c = 0; c < HID; c++) out[c] = acc[c];
}

// -------- scale g1 by dinv and convert to fp16 rows (join point) -----------
__global__ void scaleg1(int N) {
    int i = blockIdx.x * blockDim.x + threadIdx.x;   // one float4 each
    int n4 = N * CP / 4;
    if (i >= n4) return;
    float s = d_dinv[i >> 3];
    float4 v = reinterpret_cast<const float4*>(d_g1)[i];
    d_g1h[2 * i]     = __floats2half2_rn(v.x * s, v.y * s);
    d_g1h[2 * i + 1] = __floats2half2_rn(v.z * s, v.w * s);
}

// helper: accumulate a 16B (8 fp16) row chunk into acc[8]
__device__ __forceinline__ void acc_row(float* acc, uint4 r) {
    float2 p;
    p = __half22float2(*reinterpret_cast<const __half2*>(&r.x)); acc[0] += p.x; acc[1] += p.y;
    p = __half22float2(*reinterpret_cast<const __half2*>(&r.y)); acc[2] += p.x; acc[3] += p.y;
    p = __half22float2(*reinterpret_cast<const __half2*>(&r.z)); acc[4] += p.x; acc[5] += p.y;
    p = __half22float2(*reinterpret_cast<const __half2*>(&r.w)); acc[6] += p.x; acc[7] += p.y;
}

// ---- gather layer1: 4-lane groups (16 edges / 2 LDG.128), fused GEMM2 -----
__global__ void __launch_bounds__(256) gather1(const float* __restrict__ b1,
                                               const float* __restrict__ W2, int N) {
    __shared__ float Ws[HID * CP];
    for (int i = threadIdx.x; i < HID * CP; i += blockDim.x) {
        int k = i / CP, c = i % CP;
        Ws[i] = (c < NCLS) ? W2[k * NCLS + c] : 0.f;
    }
    __syncthreads();

    int tid  = threadIdx.x;
    int lane = tid & 31;
    int sub  = lane & 3;          // feature octet 0..3 (8 features each)
    int g    = lane >> 2;         // edge group 0..7
    int warp = (blockIdx.x * blockDim.x + tid) >> 5;
    int nwarps = (gridDim.x * blockDim.x) >> 5;

    float bv[8];
    {
        const float4* b14 = reinterpret_cast<const float4*>(b1);
        float4 u = b14[sub * 2], t = b14[sub * 2 + 1];
        bv[0] = u.x; bv[1] = u.y; bv[2] = u.z; bv[3] = u.w;
        bv[4] = t.x; bv[5] = t.y; bv[6] = t.z; bv[7] = t.w;
    }
    const uint4* G1 = reinterpret_cast<const uint4*>(d_g1h);

    for (int v = warp; v < N; v += nwarps) {
        int beg = d_rp[v];
        int nb  = (d_rp[v + 1] - beg) >> 4;          // blocks of 16 edges
        const int2* ip = reinterpret_cast<const int2*>(d_csr + beg);
        float acc[8];
#pragma unroll
        for (int j = 0; j < 8; j++) acc[j] = 0.f;
        int2 cur = ip[g];                             // broadcast within group
        for (int b = 0; b < nb; b++) {
            int2 nxt = ip[(b + 1) * 8 + g];           // unconditional prefetch (tail-padded)
            uint4 ra = G1[(size_t)cur.x * 4 + sub];
            uint4 rb = G1[(size_t)cur.y * 4 + sub];
            acc_row(acc, ra);
            acc_row(acc, rb);
            cur = nxt;
        }
        // reduce across the 8 edge groups (same sub holds same octet)
#pragma unroll
        for (int o = 4; o <= 16; o <<= 1)
#pragma unroll
            for (int j = 0; j < 8; j++)
                acc[j] += __shfl_xor_sync(0xffffffffu, acc[j], o);

        uint4 rs = G1[(size_t)v * 4 + sub];
        float sf[8];
        {
            float2 p;
            p = __half22float2(*reinterpret_cast<const __half2*>(&rs.x)); sf[0] = p.x; sf[1] = p.y;
            p = __half22float2(*reinterpret_cast<const __half2*>(&rs.y)); sf[2] = p.x; sf[3] = p.y;
            p = __half22float2(*reinterpret_cast<const __half2*>(&rs.z)); sf[4] = p.x; sf[5] = p.y;
            p = __half22float2(*reinterpret_cast<const __half2*>(&rs.w)); sf[6] = p.x; sf[7] = p.y;
        }
        float dv = d_dinv[v];
        float h[8];
#pragma unroll
        for (int j = 0; j < 8; j++)
            h[j] = fmaxf(dv * (acc[j] + sf[j]) + bv[j], 0.f);

        // fused GEMM2: g2[c] = dv * sum_k h[k] * W2[k][c], c = lane
        float g2c = 0.f;
#pragma unroll
        for (int k = 0; k < HID; k++) {
            float hk = __shfl_sync(0xffffffffu, h[k & 7], k >> 3);
            g2c += hk * Ws[k * CP + lane];
        }
        float val = dv * g2c;
        float partner = __shfl_down_sync(0xffffffffu, val, 1);
        if ((lane & 1) == 0)
            d_g2h[(size_t)v * 16 + (lane >> 1)] = __floats2half2_rn(val, partner);
    }
}

// ---- gather layer2: 4-lane groups + softmax + FX + bf16 + NFX -------------
__global__ void __launch_bounds__(256) gather2(const float* __restrict__ b2,
                                               float* __restrict__ fx_out, int N) {
    __shared__ float Ss[32];
    __shared__ float b2s[32];
    int tid  = threadIdx.x;
    int lane = tid & 31;
    if (tid < 32) { Ss[tid] = 0.f; b2s[tid] = (tid < NCLS) ? b2[tid] : 0.f; }
    __syncthreads();

    int sub  = lane & 3;
    int g    = lane >> 2;
    int warp = (blockIdx.x * blockDim.x + tid) >> 5;
    int nwarps = (gridDim.x * blockDim.x) >> 5;

    float bv[8];
    {
        const float4* b24 = reinterpret_cast<const float4*>(b2s);
        float4 u = b24[sub * 2], t = b24[sub * 2 + 1];
        bv[0] = u.x; bv[1] = u.y; bv[2] = u.z; bv[3] = u.w;
        bv[4] = t.x; bv[5] = t.y; bv[6] = t.z; bv[7] = t.w;
    }
    const uint4* G2 = reinterpret_cast<const uint4*>(d_g2h);
    float ls[8];
#pragma unroll
    for (int j = 0; j < 8; j++) ls[j] = 0.f;

    for (int v = warp; v < N; v += nwarps) {
        int beg = d_rp[v];
        int nb  = (d_rp[v + 1] - beg) >> 4;
        const int2* ip = reinterpret_cast<const int2*>(d_csr + beg);
        float acc[8];
#pragma unroll
        for (int j = 0; j < 8; j++) acc[j] = 0.f;
        int2 cur = ip[g];
        for (int b = 0; b < nb; b++) {
            int2 nxt = ip[(b + 1) * 8 + g];
            uint4 ra = G2[(size_t)cur.x * 4 + sub];
            uint4 rb = G2[(size_t)cur.y * 4 + sub];
            acc_row(acc, ra);
            acc_row(acc, rb);
            cur = nxt;
        }
#pragma unroll
        for (int o = 4; o <= 16; o <<= 1)
#pragma unroll
            for (int j = 0; j < 8; j++)
                acc[j] += __shfl_xor_sync(0xffffffffu, acc[j], o);

        uint4 rs = G2[(size_t)v * 4 + sub];
        float sf[8];
        {
            float2 p;
            p = __half22float2(*reinterpret_cast<const __half2*>(&rs.x)); sf[0] = p.x; sf[1] = p.y;
            p = __half22float2(*reinterpret_cast<const __half2*>(&rs.y)); sf[2] = p.x; sf[3] = p.y;
            p = __half22float2(*reinterpret_cast<const __half2*>(&rs.z)); sf[4] = p.x; sf[5] = p.y;
            p = __half22float2(*reinterpret_cast<const __half2*>(&rs.w)); sf[6] = p.x; sf[7] = p.y;
        }
        float dv = d_dinv[v];
        float lg[8];
#pragma unroll
        for (int j = 0; j < 8; j++)
            lg[j] = dv * (acc[j] + sf[j]) + bv[j];
        if (sub == 3) { lg[6] = -1e30f; lg[7] = -1e30f; }   // classes 30,31

        float mx = lg[0];
#pragma unroll
        for (int j = 1; j < 8; j++) mx = fmaxf(mx, lg[j]);
        mx = fmaxf(mx, __shfl_xor_sync(0xffffffffu, mx, 1));
        mx = fmaxf(mx, __shfl_xor_sync(0xffffffffu, mx, 2));

        float ex[8], sum = 0.f;
#pragma unroll
        for (int j = 0; j < 8; j++) { ex[j] = expf(lg[j] - mx); sum += ex[j]; }
        sum += __shfl_xor_sync(0xffffffffu, sum, 1);
        sum += __shfl_xor_sync(0xffffffffu, sum, 2);
        float inv = 1.f / sum;

        float fx[8];
#pragma unroll
        for (int j = 0; j < 8; j++) fx[j] = ex[j] * inv;   // 0 for padded classes

        if (g == 0) {
            float* base = fx_out + (size_t)v * NCLS + sub * 8;
            *reinterpret_cast<float2*>(base + 0) = make_float2(fx[0], fx[1]);
            *reinterpret_cast<float2*>(base + 2) = make_float2(fx[2], fx[3]);
            *reinterpret_cast<float2*>(base + 4) = make_float2(fx[4], fx[5]);
            if (sub < 3)
                *reinterpret_cast<float2*>(base + 6) = make_float2(fx[6], fx[7]);

            __nv_bfloat162 q0 = __floats2bfloat162_rn(fx[0], fx[1]);
            __nv_bfloat162 q1 = __floats2bfloat162_rn(fx[2], fx[3]);
            __nv_bfloat162 q2 = __floats2bfloat162_rn(fx[4], fx[5]);
            __nv_bfloat162 q3 = __floats2bfloat162_rn(fx[6], fx[7]);
            uint4 pk;
            pk.x = *reinterpret_cast<unsigned int*>(&q0);
            pk.y = *reinterpret_cast<unsigned int*>(&q1);
            pk.z = *reinterpret_cast<unsigned int*>(&q2);
            pk.w = *reinterpret_cast<unsigned int*>(&q3);
            reinterpret_cast<uint4*>(d_fx16 + (size_t)v * 16)[sub] = pk;

#pragma unroll
            for (int j = 0; j < 8; j++) ls[j] += log1pf(-fx[j] * fx[j]);
        }
    }
    if (g == 0) {
#pragma unroll
        for (int j = 0; j < 8; j++) atomicAdd(&Ss[sub * 8 + j], ls[j]);
    }
    __syncthreads();
    if (tid < NCLS) d_partialS[tid * gridDim.x + blockIdx.x] = Ss[tid];
}

// ------- FF + MSE partials (2 edges per 4-lane group) + d_cnt re-zero ------
__global__ void ff_k(const float* __restrict__ ep, int E, int N) {
    __shared__ float sAcc;
    int tid = threadIdx.x;
    if (tid == 0) sAcc = 0.f;
    __syncthreads();

    int idx = blockIdx.x * blockDim.x + tid;

    // re-zero d_cnt for the next call (all consumers ran earlier this call)
    int nthreads = gridDim.x * blockDim.x;
    for (int i = idx; i <= N; i += nthreads) d_cnt[i] = 0;

    int grp = idx >> 2, c = idx & 3;
    int e0 = grp * 2;
    int nGrp = (E + 1) >> 1;
    bool v0 = (grp < nGrp) && (e0 < E);
    bool v1 = (grp < nGrp) && (e0 + 1 < E);

    float p0 = 0.f, p1 = 0.f;
    if (v0) {
        int s0 = d_src32[e0], dd0 = d_dst32[e0];
        uint4 A0 = reinterpret_cast<const uint4*>(d_fx16 + (size_t)s0  * 16)[c];
        uint4 B0 = reinterpret_cast<const uint4*>(d_fx16 + (size_t)dd0 * 16)[c];
        const unsigned int aw[4] = {A0.x, A0.y, A0.z, A0.w};
        const unsigned int bw[4] = {B0.x, B0.y, B0.z, B0.w};
#pragma unroll
        for (int j = 0; j < 4; j++) {
            float2 af = __bfloat1622float2(*reinterpret_cast<const __nv_bfloat162*>(&aw[j]));
            float2 bf = __bfloat1622float2(*reinterpret_cast<const __nv_bfloat162*>(&bw[j]));
            p0 += af.x * bf.x + af.y * bf.y;
        }
    }
    if (v1) {
        int s1 = d_src32[e0 + 1], dd1 = d_dst32[e0 + 1];
        uint4 A1 = reinterpret_cast<const uint4*>(d_fx16 + (size_t)s1  * 16)[c];
        uint4 B1 = reinterpret_cast<const uint4*>(d_fx16 + (size_t)dd1 * 16)[c];
        const unsigned int aw[4] = {A1.x, A1.y, A1.z, A1.w};
        const unsigned int bw[4] = {B1.x, B1.y, B1.z, B1.w};
#pragma unroll
        for (int j = 0; j < 4; j++) {
            float2 af = __bfloat1622float2(*reinterpret_cast<const __nv_bfloat162*>(&aw[j]));
            float2 bf = __bfloat1622float2(*reinterpret_cast<const __nv_bfloat162*>(&bw[j]));
            p1 += af.x * bf.x + af.y * bf.y;
        }
    }

    p0 += __shfl_down_sync(0xffffffffu, p0, 1);
    p0 += __shfl_down_sync(0xffffffffu, p0, 2);
    p1 += __shfl_down_sync(0xffffffffu, p1, 1);
    p1 += __shfl_down_sync(0xffffffffu, p1, 2);

    float d2 = 0.f;
    if (c == 0) {
        if (v0) { float f = p0 - ep[e0];     d2 += f * f; }
        if (v1) { float f = p1 - ep[e0 + 1]; d2 += f * f; }
    }
    d2 += __shfl_down_sync(0xffffffffu, d2, 4);
    d2 += __shfl_down_sync(0xffffffffu, d2, 8);
    d2 += __shfl_down_sync(0xffffffffu, d2, 16);
    if ((tid & 31) == 0) atomicAdd(&sAcc, d2);
    __syncthreads();
    if (tid == 0) d_partialM[blockIdx.x] = sAcc;
}

// ---------------- finalize loss -------------------------------------------
__global__ void fin_k(float* __restrict__ out, int N, int E, int out_size, int nb_m) {
    __shared__ double sS[32];
    __shared__ double red[32];
    int tid = threadIdx.x, w = tid >> 5, lane = tid & 31;

    if (w < NCLS) {
        float s = 0.f;
        for (int k = lane; k < G2MAX; k += 32) s += d_partialS[w * G2MAX + k];
#pragma unroll
        for (int o = 16; o; o >>= 1) s += __shfl_down_sync(0xffffffffu, s, o);
        if (lane == 0) sS[w] = (double)s;
    }

    double m = 0.0;
    for (int k = tid; k < nb_m; k += 1024) m += (double)d_partialM[k];
#pragma unroll
    for (int o = 16; o; o >>= 1) m += __shfl_down_sync(0xffffffffu, m, o);
    if (lane == 0) red[w] = m;
    __syncthreads();

    if (tid == 0) {
        double mm = 0.0;
        for (int i = 0; i < 32; i++) mm += red[i];
        double preg = 0.0;
        for (int c = 0; c < NCLS; c++)
            preg -= log(1.0001 - exp(sS[c]));
        double loss = mm / (double)E + REG_C * preg;
        if (out_size > N * NCLS) out[(size_t)N * NCLS] = (float)loss;
    }
}

// ---------------- launch ---------------------------------------------------
extern "C" void kernel_launch(void* const* d_in, const int* in_sizes, int n_in,
                              void* d_out, int out_size) {
    const float* x   = (const float*)d_in[0];
    const void*  ei  = d_in[1];
    const float* ep  = (const float*)d_in[2];
    const float* W1  = (const float*)d_in[3];
    const float* b1  = (const float*)d_in[4];
    const float* W2  = (const float*)d_in[5];
    const float* b2  = (const float*)d_in[6];
    float* out = (float*)d_out;

    int N = in_sizes[0] / IN_DIM;    // 100000
    int E = in_sizes[2];             // 3200000
    int nb_scan = (N + 1 + 1023) / 1024;
    long long ff_threads = ((long long)E + 1) / 2 * 4;
    int nb_ff   = (int)((ff_threads + 1023) / 1024);
    int n4 = N * CP / 4;

    static cudaStream_t s_aux = nullptr;
    static cudaEvent_t ev_root = nullptr, ev_scan1 = nullptr, ev_g1 = nullptr;
    if (s_aux == nullptr) {
        cudaStreamCreateWithFlags(&s_aux, cudaStreamNonBlocking);
        cudaEventCreateWithFlags(&ev_root, cudaEventDisableTiming);
        cudaEventCreateWithFlags(&ev_scan1, cudaEventDisableTiming);
        cudaEventCreateWithFlags(&ev_g1,   cudaEventDisableTiming);
    }

    const int T = 256;

    // fork: aux stream runs gemm1_raw concurrently with CSR build
    cudaEventRecord(ev_root, 0);
    cudaStreamWaitEvent(s_aux, ev_root, 0);
    gemm1_raw<<<(N + 127) / 128, 128, 0, s_aux>>>(x, W1, N);

    // main chain: CSR build
    count_convert<<<(E + T - 1) / T, T>>>(ei, E);
    scan1        <<<nb_scan, 1024>>>(N);
    cudaEventRecord(ev_scan1, 0);

    cudaStreamWaitEvent(s_aux, ev_scan1, 0);
    scaleg1<<<(n4 + T - 1) / T, T, 0, s_aux>>>(N);
    cudaEventRecord(ev_g1, s_aux);

    scan3        <<<nb_scan, 1024>>>(N);
    fill_k       <<<(E + T - 1) / T, T>>>(E);

    cudaStreamWaitEvent(0, ev_g1, 0);
    gather1      <<<2048, 256>>>(b1, W2, N);
    gather2      <<<G2MAX, 256>>>(b2, out, N);
    ff_k         <<<nb_ff, 1024>>>(ep, E, N);
    fin_k        <<<1, 1024>>>(out, N, E, out_size, nb_ff);
}